// round 12
// baseline (speedup 1.0000x reference)
#include <cuda_runtime.h>
#include <cuda_fp16.h>
#include <cstdint>

// Problem constants
#define NTOK 65536
#define IN   512
#define OUT  512
#define NE   8
#define NS   64

// GEMM tiling: CTA 128x128, 4 warps of 64x64
#define TM 128
#define TN 128
#define KC 64
#define NCHUNK (IN / KC)          // 8
#define MAXT 576
#define LDSS 144                  // 128B data + 16B pad: conflict-free ldmatrix

#define A_PLANE (TM * LDSS)       // 18432
#define B_PLANE (TN * LDSS)       // 18432
#define OFF_B   A_PLANE
#define STAGE_BYTES (A_PLANE + B_PLANE)       // 36864
#define OFF_PERM (2 * STAGE_BYTES)            // 73728
#define GSMEM (OFF_PERM + 512)                // 74240 (2 CTAs/SM)

#define CONV_CHUNKS 256           // convert work units (32768 float4 each)

// ---------------- device scratch (static; no allocation) ---------------------
__device__ __half g_xh[(size_t)NTOK * IN];    // fp16(x), ORIGINAL token order
__device__ __half g_Mh[(size_t)NS * OUT * IN];
__device__ int g_counts[NS];          // zeroed by plan block after use
__device__ int g_cursor[NS];
__device__ int g_perm[NTOK];
__device__ int g_tile_sys[MAXT];
__device__ int g_tile_start[MAXT];
__device__ int g_tile_rows[MAXT];
__device__ int g_hist_done;           // reset by plan block
__device__ int g_plan_flag;           // reset by gemm block (0,0)
__device__ int g_conv_ctr;            // reset by gemm block (0,0)

// ---------------- helpers -----------------------------------------------------
__device__ __forceinline__ uint32_t smem_u32(const void* p) {
    uint32_t a;
    asm("{ .reg .u64 t; cvta.to.shared.u64 t, %1; cvt.u32.u64 %0, t; }"
        : "=r"(a) : "l"(p));
    return a;
}
__device__ __forceinline__ void cpa16(uint32_t dst, const void* src) {
    asm volatile("cp.async.cg.shared.global [%0], [%1], 16;"
                 :: "r"(dst), "l"(src) : "memory");
}
__device__ __forceinline__ void ldsm4(uint32_t* r, uint32_t addr) {
    asm volatile("ldmatrix.sync.aligned.m8n8.x4.shared.b16 {%0,%1,%2,%3}, [%4];"
                 : "=r"(r[0]), "=r"(r[1]), "=r"(r[2]), "=r"(r[3]) : "r"(addr));
}
__device__ __forceinline__ void mma16816(float* c, const uint32_t* a,
                                         uint32_t b0, uint32_t b1) {
    asm volatile(
        "mma.sync.aligned.m16n8k16.row.col.f32.f16.f16.f32 "
        "{%0,%1,%2,%3}, {%4,%5,%6,%7}, {%8,%9}, {%0,%1,%2,%3};"
        : "+f"(c[0]), "+f"(c[1]), "+f"(c[2]), "+f"(c[3])
        : "r"(a[0]), "r"(a[1]), "r"(a[2]), "r"(a[3]), "r"(b0), "r"(b1));
}
__device__ __forceinline__ uint2 round4h(float4 v) {
    __half2 h01 = __floats2half2_rn(v.x, v.y);
    __half2 h23 = __floats2half2_rn(v.z, v.w);
    return make_uint2(*(uint32_t*)&h01, *(uint32_t*)&h23);
}

// ---------------- kernel 1: fused prep with work-stealing convert -------------
// blocks 0..63:    hist (last block runs plan, sets g_plan_flag)
// blocks 64..127:  scatter (spins on flag for bases)
// blocks 128..191: mix weights -> fp16
// After role work, ALL 512 blocks join the atomic-counter convert loop.
__global__ __launch_bounds__(256) void prep_kernel(const int* __restrict__ bi,
                                                   const float* __restrict__ x,
                                                   const float* __restrict__ W,
                                                   const float* __restrict__ coeff) {
    int bx = blockIdx.x;
    int tid = threadIdx.x;

    if (bx < 64) {
        // ---- histogram over tokens [bx*1024, +1024) ----
        __shared__ int h[NS];
        __shared__ int lastdone;
        if (tid < NS) h[tid] = 0;
        __syncthreads();
        int base = bx * 1024;
#pragma unroll
        for (int j = 0; j < 4; ++j)
            atomicAdd(&h[bi[base + j * 256 + tid]], 1);
        __syncthreads();
        if (tid < NS && h[tid] != 0) atomicAdd(&g_counts[tid], h[tid]);
        __threadfence();
        __syncthreads();
        if (tid == 0) lastdone = atomicAdd(&g_hist_done, 1);
        __syncthreads();
        if (lastdone == 63) {
            // ---- plan (runs in the last-finishing hist block) ----
            __threadfence();
            __shared__ int cnt[NS], offs[NS], tbase[NS];
            if (tid < NS) cnt[tid] = g_counts[tid];
            __syncthreads();
            if (tid == 0) {
                int off = 0, tb = 0;
                for (int s = 0; s < NS; ++s) {
                    offs[s] = off; tbase[s] = tb;
                    off += cnt[s];
                    tb  += (cnt[s] + TM - 1) / TM;
                }
            }
            __syncthreads();
            for (int i = tid; i < MAXT; i += 256) g_tile_rows[i] = 0;
            __syncthreads();
            if (tid < NS) {
                int s = tid, c = cnt[s], nt = (c + TM - 1) / TM;
                int tb = tbase[s], off = offs[s];
                g_cursor[s] = off;
                for (int k = 0; k < nt; ++k) {
                    g_tile_sys[tb + k]   = s;
                    g_tile_start[tb + k] = off + k * TM;
                    int rem = c - k * TM;
                    g_tile_rows[tb + k]  = rem < TM ? rem : TM;
                }
                g_counts[s] = 0;           // reset for next replay
            }
            if (tid == 0) g_hist_done = 0; // reset for next replay
            __threadfence();
            __syncthreads();
            if (tid == 0) atomicExch(&g_plan_flag, 1);   // release
        }
    } else if (bx < 128) {
        // ---- scatter tokens [(bx-64)*1024, +1024): write g_perm ----
        __shared__ int lc[NS], lbase[NS];
        if (tid < NS) lc[tid] = 0;
        __syncthreads();
        int base = (bx - 64) * 1024;
        int myn[4], mys[4], myr[4];
#pragma unroll
        for (int j = 0; j < 4; ++j) {
            int n = base + j * 256 + tid;
            int s = bi[n];
            myn[j] = n; mys[j] = s;
            myr[j] = atomicAdd(&lc[s], 1);
        }
        __syncthreads();
        if (tid == 0) {
            while (atomicAdd(&g_plan_flag, 0) == 0) __nanosleep(200);
        }
        __syncthreads();
        __threadfence();               // acquire
        if (tid < NS && lc[tid] > 0) lbase[tid] = atomicAdd(&g_cursor[tid], lc[tid]);
        __syncthreads();
#pragma unroll
        for (int j = 0; j < 4; ++j)
            g_perm[lbase[mys[j]] + myr[j]] = myn[j];
    } else if (bx < 192) {
        // ---- mix: M[s] = sum_e c[s,e] * W[e], rounded fp16 ----
        __shared__ float sc[NS * NE];
        for (int i = tid; i < NS * NE; i += 256) sc[i] = coeff[i];
        __syncthreads();
#pragma unroll
        for (int quarter = 0; quarter < 4; ++quarter) {
            int idx = (bx - 128) * 1024 + quarter * 256 + tid;  // over OUT*IN/4
            int o  = idx >> 7;
            int q  = idx & 127;
            int i4 = q * 4;
            float4 w[NE];
#pragma unroll
            for (int e = 0; e < NE; ++e)
                w[e] = *(const float4*)(W + (size_t)e * OUT * IN + o * IN + i4);
#pragma unroll 4
            for (int s = 0; s < NS; ++s) {
                float4 acc = make_float4(0.f, 0.f, 0.f, 0.f);
#pragma unroll
                for (int e = 0; e < NE; ++e) {
                    float c = sc[s * NE + e];
                    acc.x = fmaf(c, w[e].x, acc.x);
                    acc.y = fmaf(c, w[e].y, acc.y);
                    acc.z = fmaf(c, w[e].z, acc.z);
                    acc.w = fmaf(c, w[e].w, acc.w);
                }
                ((uint2*)(g_Mh + (size_t)(s * OUT + o) * IN))[q] = round4h(acc);
            }
        }
    }

    // ---- work-stealing convert: x fp32 -> g_xh fp16 (original order) ----
    const float4* xin = (const float4*)x;
    uint2* xo = (uint2*)g_xh;
    for (;;) {
        __shared__ int cchunk;
        __syncthreads();
        if (tid == 0) cchunk = atomicAdd(&g_conv_ctr, 1);
        __syncthreads();
        int c = cchunk;
        if (c >= CONV_CHUNKS) break;
        int base = c * 32768 + tid;     // 32768 float4 per chunk
#pragma unroll 4
        for (int i = 0; i < 128; ++i) {
            int gidx = base + i * 256;
            xo[gidx] = round4h(xin[gidx]);
        }
    }
}

// ---------------- kernel 2: grouped GEMM, fp16, 4 fat warps, 2 CTAs/SM --------
// CTA: 128 tokens x 128 outputs; 4 warps (2x2), warp tile 64x64.
// K=512, 8 chunks of 64, fully unrolled; 2-stage cp.async; kk double-buffer.
__global__ __launch_bounds__(128, 2) void gemm_kernel(const float* __restrict__ bias,
                                                      float* __restrict__ out) {
    if (blockIdx.x == 0 && blockIdx.y == 0 && threadIdx.x == 0) {
        g_plan_flag = 0;               // reset for next replay
        g_conv_ctr  = 0;
    }

    int bt = blockIdx.y;
    int rows = g_tile_rows[bt];
    if (rows == 0) return;
    int sys       = g_tile_sys[bt];
    int row_start = g_tile_start[bt];
    int col0      = blockIdx.x * TN;

    extern __shared__ __align__(16) char smem[];
    uint32_t sm = smem_u32(smem);
    int tid = threadIdx.x, lane = tid & 31, wid = tid >> 5;
    int wm = wid >> 1, wn = wid & 1;      // 2 x 2 warp grid, 64x64 each

    int* sperm = (int*)(smem + OFF_PERM);
    if (tid < TM) {
        int rsi = row_start + tid;
        if (rsi > NTOK - 1) rsi = NTOK - 1;
        sperm[tid] = g_perm[rsi];
    }
    __syncthreads();                    // sperm visible to loaders

    // loaders: 128 threads; A: 8 rows/thread, B: 8 rows/thread, 16B segs
    int row16 = tid >> 3;     // 0..15
    int seg   = tid & 7;
    const __half* bpt = g_Mh + (size_t)sys * OUT * IN
                      + (size_t)(col0 + row16) * IN + seg * 8;
    uint32_t dstA = sm + row16 * LDSS + seg * 16;

    auto load_chunk = [&](uint32_t stoff, int c) {
#pragma unroll
        for (int h = 0; h < 8; ++h) {
            int tok = sperm[row16 + h * 16];
            cpa16(stoff + dstA + h * 16 * LDSS,
                  g_xh + (size_t)tok * IN + seg * 8 + c * KC);
        }
#pragma unroll
        for (int h = 0; h < 8; ++h)
            cpa16(stoff + dstA + OFF_B + h * 16 * LDSS, bpt + (size_t)h * 16 * IN + c * KC);
        asm volatile("cp.async.commit_group;" ::: "memory");
    };

    float acc[4][8][4];
#pragma unroll
    for (int mf = 0; mf < 4; ++mf)
#pragma unroll
        for (int nf = 0; nf < 8; ++nf)
#pragma unroll
            for (int r = 0; r < 4; ++r) acc[mf][nf][r] = 0.f;

    load_chunk(0, 0);

    int lrow = lane & 15, kseg = lane >> 4;
    uint32_t a_base = sm + (uint32_t)((wm * 64 + lrow) * LDSS + kseg * 16);
    uint32_t b_base = sm + (uint32_t)(OFF_B + (wn * 64 + lrow) * LDSS + kseg * 16);

    uint32_t aa[2][4][4], bb[2][4][4];

#pragma unroll
    for (int c = 0; c < NCHUNK; ++c) {
        asm volatile("cp.async.wait_group 0;" ::: "memory");
        __syncthreads();
        if (c + 1 < NCHUNK) load_chunk(((c + 1) & 1) * STAGE_BYTES, c + 1);

        uint32_t so = (uint32_t)((c & 1) * STAGE_BYTES);

        // prologue: fragments for kk=0
#pragma unroll
        for (int mf = 0; mf < 4; ++mf)
            ldsm4(aa[0][mf], a_base + so + mf * 16 * LDSS);
#pragma unroll
        for (int bf = 0; bf < 4; ++bf)
            ldsm4(bb[0][bf], b_base + so + bf * 16 * LDSS);

#pragma unroll
        for (int kk = 0; kk < 4; ++kk) {
            int cur = kk & 1;
            if (kk < 3) {
                int nxt = cur ^ 1;
#pragma unroll
                for (int mf = 0; mf < 4; ++mf)
                    ldsm4(aa[nxt][mf], a_base + so + mf * 16 * LDSS + (kk + 1) * 32);
#pragma unroll
                for (int bf = 0; bf < 4; ++bf)
                    ldsm4(bb[nxt][bf], b_base + so + bf * 16 * LDSS + (kk + 1) * 32);
            }
#pragma unroll
            for (int mf = 0; mf < 4; ++mf)
#pragma unroll
                for (int nf = 0; nf < 8; ++nf)
                    mma16816(acc[mf][nf], aa[cur][mf],
                             bb[cur][nf >> 1][nf & 1], bb[cur][nf >> 1][(nf & 1) + 2]);
        }
    }

    // ---------------- epilogue: bias + scatter -------------------------------
    int g  = lane >> 2;
    int tc = (lane & 3) * 2;
    const float* bptr = bias + col0 + wn * 64 + tc;
    float2 bv[8];
#pragma unroll
    for (int nf = 0; nf < 8; ++nf)
        bv[nf] = make_float2(bptr[nf * 8], bptr[nf * 8 + 1]);

#pragma unroll
    for (int mf = 0; mf < 4; ++mf) {
#pragma unroll
        for (int rh = 0; rh < 2; ++rh) {
            int lr = wm * 64 + mf * 16 + rh * 8 + g;
            if (lr < rows) {
                float* orow = out + (size_t)sperm[lr] * OUT + col0 + wn * 64 + tc;
#pragma unroll
                for (int nf = 0; nf < 8; ++nf) {
                    float2 v = make_float2(acc[mf][nf][rh * 2]     + bv[nf].x,
                                           acc[mf][nf][rh * 2 + 1] + bv[nf].y);
                    *(float2*)(orow + nf * 8) = v;
                }
            }
        }
    }
}

// ---------------- launch -----------------------------------------------------
extern "C" void kernel_launch(void* const* d_in, const int* in_sizes, int n_in,
                              void* d_out, int out_size) {
    const float* x     = (const float*)d_in[0];
    const float* coeff = (const float*)d_in[1];
    const int*   bidx  = (const int*)d_in[2];
    const float* W     = (const float*)d_in[3];
    const float* bias  = (const float*)d_in[4];
    float*       out   = (float*)d_out;

    cudaFuncSetAttribute(gemm_kernel, cudaFuncAttributeMaxDynamicSharedMemorySize,
                         GSMEM);

    prep_kernel<<<512, 256>>>(bidx, x, W, coeff);
    gemm_kernel<<<dim3(OUT / TN, MAXT), 128, GSMEM>>>(bias, out);
}